// round 13
// baseline (speedup 1.0000x reference)
#include <cuda_runtime.h>
#include <cuda_fp16.h>
#include <cstdint>

#define IN_DIM   4096
#define OUT_DIM  4096
#define TOKENS   4096
#define RANK     64
#define VDIM     8
#define NIDX     (IN_DIM / VDIM)

// ---------------------------------------------------------------------------
// Device-global scratch. Everything lives in PERMUTED input space:
//   xp[m][j'] = x[m][invperm[j']],  W'[o][j'] = Q[o][j'] + L'[o][j']
// ---------------------------------------------------------------------------
__device__ __half g_Whi[(size_t)OUT_DIM * IN_DIM];
__device__ __half g_Wlos[(size_t)OUT_DIM * IN_DIM];   // (W' - Whi) * 32
__device__ __half g_xp[(size_t)TOKENS * IN_DIM];
__device__ int    g_invperm[IN_DIM];

// ---------------------------------------------------------------------------
// PTX helpers (baseline compute_100-legal)
// ---------------------------------------------------------------------------
static __device__ __forceinline__ uint32_t smem_u32(const void* p) {
    uint32_t a;
    asm("{ .reg .u64 t; cvta.to.shared.u64 t, %1; cvt.u32.u64 %0, t; }" : "=r"(a) : "l"(p));
    return a;
}

#define CP_ASYNC16(dst, src) \
    asm volatile("cp.async.cg.shared.global [%0], [%1], 16;\n" :: "r"(dst), "l"(src))
#define CP_COMMIT() asm volatile("cp.async.commit_group;\n" ::: "memory")
#define CP_WAIT0()  asm volatile("cp.async.wait_group 0;\n" ::: "memory")

#define LDSM_X4(r0, r1, r2, r3, addr) \
    asm volatile("ldmatrix.sync.aligned.m8n8.x4.shared.b16 {%0,%1,%2,%3}, [%4];" \
        : "=r"(r0), "=r"(r1), "=r"(r2), "=r"(r3) : "r"(addr))

#define MMA16816F(c, a, b) \
    asm volatile("mma.sync.aligned.m16n8k16.row.col.f32.f16.f16.f32 " \
        "{%0,%1,%2,%3}, {%4,%5,%6,%7}, {%8,%9}, {%0,%1,%2,%3};" \
        : "+f"((c)[0]), "+f"((c)[1]), "+f"((c)[2]), "+f"((c)[3]) \
        : "r"((a)[0]), "r"((a)[1]), "r"((a)[2]), "r"((a)[3]), \
          "r"((b)[0]), "r"((b)[1]))

#define HMUL2(d, a, s) \
    asm("mul.f16x2 %0, %1, %2;" : "=r"(d) : "r"(a), "r"(s))

// half2(1/32, 1/32) — exponent-only scale, exact
#define SC_1_32 0x28002800u

// ---------------------------------------------------------------------------
// Kernel 0: invperm[perm[j]] = j
// ---------------------------------------------------------------------------
__global__ void invperm_kernel(const int* __restrict__ perm)
{
    int j = blockIdx.x * 256 + threadIdx.x;
    g_invperm[perm[j]] = j;
}

// ---------------------------------------------------------------------------
// Kernel 1 (fused): interleaved block roles.
//   odd blocks : convert one x row -> xp (fp16, permuted)   [memory-bound]
//   even blocks: dequant a 32x128 W' tile (hi + 32*lo)      [compute-bound]
// Interleaving co-schedules both kinds per SM -> overlap.
// ---------------------------------------------------------------------------
__global__ __launch_bounds__(256) void fused_pre_kernel(
    const float* __restrict__ x,
    const float* __restrict__ centroids, const int* __restrict__ indices,
    const float* __restrict__ wscale, const float* __restrict__ wbias,
    const float* __restrict__ U, const float* __restrict__ S,
    const float* __restrict__ Vt)
{
    const int tid = threadIdx.x;

    if (blockIdx.x & 1) {
        // ---- convert role: row m of x -> g_xp ----
        const int m = blockIdx.x >> 1;
        const float* xr = x + (size_t)m * IN_DIM;
        #pragma unroll
        for (int t = 0; t < 4; t++) {
            int j = (t * 256 + tid) * 4;
            const int4 inv = *(const int4*)(g_invperm + j);
            float v0 = xr[inv.x], v1 = xr[inv.y], v2 = xr[inv.z], v3 = xr[inv.w];
            size_t i = (size_t)m * IN_DIM + j;
            *(__half2*)(g_xp + i)     = __floats2half2_rn(v0, v1);
            *(__half2*)(g_xp + i + 2) = __floats2half2_rn(v2, v3);
        }
        return;
    }

    // ---- dequant role ----
    __shared__ float s_us[32 * RANK];      // [ol][r], 8 KB
    __shared__ float s_vt[RANK * 128];     // [r][j'], 32 KB (gathered by invperm)
    __shared__ int   s_inv[128];

    const int d  = blockIdx.x >> 1;        // 0..4095
    const int j0 = (d & 31) * 128;
    const int o0 = (d >> 5) * 32;
    const int tr = tid >> 5;               // 0..7  -> rows tr*4 .. tr*4+3
    const int tc = tid & 31;               // 0..31 -> cols tc*4 .. tc*4+3

    if (tid < 128) s_inv[tid] = g_invperm[j0 + tid];
    __syncthreads();

    for (int i = tid; i < 32 * RANK; i += 256) {
        int o = i >> 6, r = i & (RANK - 1);
        s_us[i] = U[(size_t)(o0 + o) * RANK + r] * S[r];
    }
    for (int i = tid; i < RANK * 128; i += 256) {
        int r = i >> 7, j = i & 127;
        s_vt[i] = Vt[(size_t)r * IN_DIM + s_inv[j]];
    }
    __syncthreads();

    // quantized part: 1 index + 1 float4 centroid load per row
    const int grp  = (j0 + tc * 4) >> 3;
    const int coff = (tc * 4) & 7;
    float acc[4][4];
    #pragma unroll
    for (int i = 0; i < 4; i++) {
        int o = o0 + tr * 4 + i;
        int ci = indices[(size_t)o * NIDX + grp];
        float4 cv = *(const float4*)(centroids + (size_t)ci * VDIM + coff);
        float sc = wscale[o], bi = wbias[o];
        acc[i][0] = cv.x * sc + bi;
        acc[i][1] = cv.y * sc + bi;
        acc[i][2] = cv.z * sc + bi;
        acc[i][3] = cv.w * sc + bi;
    }

    // low-rank: 4x4 register block GEMM over RANK
    #pragma unroll
    for (int rb = 0; rb < RANK; rb += 4) {
        float4 us4[4];
        #pragma unroll
        for (int i = 0; i < 4; i++)
            us4[i] = *(const float4*)&s_us[(tr * 4 + i) * RANK + rb];
        #pragma unroll
        for (int rr = 0; rr < 4; rr++) {
            float4 v = *(const float4*)&s_vt[(rb + rr) * 128 + tc * 4];
            #pragma unroll
            for (int i = 0; i < 4; i++) {
                float u = (&us4[i].x)[rr];
                acc[i][0] += u * v.x;
                acc[i][1] += u * v.y;
                acc[i][2] += u * v.z;
                acc[i][3] += u * v.w;
            }
        }
    }

    // split + store
    #pragma unroll
    for (int i = 0; i < 4; i++) {
        size_t idx = (size_t)(o0 + tr * 4 + i) * IN_DIM + j0 + tc * 4;
        __half h[4], l[4];
        #pragma unroll
        for (int jj = 0; jj < 4; jj++) {
            h[jj] = __float2half_rn(acc[i][jj]);
            l[jj] = __float2half_rn((acc[i][jj] - __half2float(h[jj])) * 32.0f);
        }
        *(__half2*)(g_Whi  + idx)     = __halves2half2(h[0], h[1]);
        *(__half2*)(g_Whi  + idx + 2) = __halves2half2(h[2], h[3]);
        *(__half2*)(g_Wlos + idx)     = __halves2half2(l[0], l[1]);
        *(__half2*)(g_Wlos + idx + 2) = __halves2half2(l[2], l[3]);
    }
}

// ---------------------------------------------------------------------------
// Kernel 2: HMMA GEMM, 2-pass fp16 split:
//   C = xp*Whi + (xp/32)*Wlos + bias   (fp32 accumulate)
//   CTA 128x128, BK=64, 8 warps, 2-stage pipeline with ONE sync per chunk:
//   at iter i the sync certifies stage (i-1)&1 free; (i-1)&1 == (i+1)&1, so
//   chunk i+1 is issued there immediately after the sync and its loads
//   overlap the whole compute phase. 64 barriers total. 2 CTAs/SM.
// ---------------------------------------------------------------------------
#define BM 128
#define BN 128
#define BK 64
#define GKP 72            // padded k-stride (elements); rows at distinct 16B banks
#define NCHUNK (IN_DIM / BK)

#define TILE_BYTES (BM * GKP * 2)          // 18432
#define T_AHI 0
#define T_BHI (1 * TILE_BYTES)
#define T_BLO (2 * TILE_BYTES)
#define STAGE_SZ (3 * TILE_BYTES)          // 55296
#define SMEM_TOTAL (2 * STAGE_SZ)          // 110592  (x2 CTAs = 221184 <= 228KB)

static __device__ __forceinline__ void load_chunk(uint32_t stage, int m0, int n0,
                                                  int k0, int tid)
{
    #pragma unroll
    for (int t = 0; t < 4; t++) {
        int idx = t * 256 + tid;
        int row = idx >> 3;                 // 0..127
        int c   = idx & 7;                  // 16B chunk within 128B row
        uint32_t off = (uint32_t)(row * GKP + c * 8) * 2;
        size_t ga = (size_t)(m0 + row) * IN_DIM + k0 + c * 8;
        size_t gb = (size_t)(n0 + row) * IN_DIM + k0 + c * 8;
        CP_ASYNC16(stage + T_AHI + off, (const char*)(g_xp   + ga));
        CP_ASYNC16(stage + T_BHI + off, (const char*)(g_Whi  + gb));
        CP_ASYNC16(stage + T_BLO + off, (const char*)(g_Wlos + gb));
    }
    CP_COMMIT();
}

__global__ __launch_bounds__(256, 2) void gemm_kernel(
    const float* __restrict__ bias, float* __restrict__ C)
{
    extern __shared__ char smem[];
    const uint32_t sb = smem_u32(smem);
    const int tid  = threadIdx.x;
    const int wid  = tid >> 5;
    const int lane = tid & 31;
    const int wm   = wid >> 2;              // 0..1 : warp row (64 m each)
    const int wn   = wid & 3;               // 0..3 : warp col (32 n each)
    const int m0   = blockIdx.y * BM;
    const int n0   = blockIdx.x * BN;

    const uint32_t a_off =
        (uint32_t)(((wm * 64 + (lane & 15)) * GKP + ((lane >> 4) & 1) * 8) * 2);
    const uint32_t b_off =
        (uint32_t)(((wn * 32 + ((lane >> 4) & 1) * 8 + (lane & 7)) * GKP +
                    ((lane >> 3) & 1) * 8) * 2);

    float acc[4][4][4];
    #pragma unroll
    for (int i = 0; i < 4; i++)
        #pragma unroll
        for (int j = 0; j < 4; j++)
            #pragma unroll
            for (int k = 0; k < 4; k++) acc[i][j][k] = 0.f;

    // prologue: chunk 0 -> stage 0
    load_chunk(sb, m0, n0, 0, tid);

    for (int i = 0; i < NCHUNK; i++) {
        const uint32_t stage = sb + (i & 1) * STAGE_SZ;

        // only chunk i's group can be in flight here -> wait_group 0
        CP_WAIT0();
        __syncthreads();   // (a) chunk i visible to all, (b) stage (i+1)&1 free

        if (i + 1 < NCHUNK)
            load_chunk(sb + ((i + 1) & 1) * STAGE_SZ, m0, n0, (i + 1) * BK, tid);

        #pragma unroll
        for (int ks = 0; ks < 4; ks++) {
            const uint32_t kb = ks * 32;    // 16 elems * 2B
            uint32_t ahi[4][4], ahs[4][4], bhi[4][2], blo[4][2];
            #pragma unroll
            for (int mi = 0; mi < 4; mi++) {
                uint32_t ad = stage + a_off + mi * (16 * GKP * 2) + kb;
                LDSM_X4(ahi[mi][0], ahi[mi][1], ahi[mi][2], ahi[mi][3], ad + T_AHI);
                #pragma unroll
                for (int q = 0; q < 4; q++)
                    HMUL2(ahs[mi][q], ahi[mi][q], SC_1_32);
            }
            #pragma unroll
            for (int g = 0; g < 2; g++) {
                uint32_t bd = stage + b_off + g * (16 * GKP * 2) + kb;
                LDSM_X4(bhi[2*g][0], bhi[2*g][1], bhi[2*g+1][0], bhi[2*g+1][1], bd + T_BHI);
                LDSM_X4(blo[2*g][0], blo[2*g][1], blo[2*g+1][0], blo[2*g+1][1], bd + T_BLO);
            }
            #pragma unroll
            for (int mi = 0; mi < 4; mi++)
                #pragma unroll
                for (int nj = 0; nj < 4; nj++) {
                    MMA16816F(acc[mi][nj], ahi[mi], bhi[nj]);
                    MMA16816F(acc[mi][nj], ahs[mi], blo[nj]);
                }
        }
    }

    #pragma unroll
    for (int mi = 0; mi < 4; mi++) {
        int r = m0 + wm * 64 + mi * 16 + (lane >> 2);
        #pragma unroll
        for (int nj = 0; nj < 4; nj++) {
            int c = n0 + wn * 32 + nj * 8 + (lane & 3) * 2;
            float2 bv = *(const float2*)(bias + c);
            float2 v0 = { acc[mi][nj][0] + bv.x, acc[mi][nj][1] + bv.y };
            float2 v1 = { acc[mi][nj][2] + bv.x, acc[mi][nj][3] + bv.y };
            *(float2*)(C + (size_t)r * OUT_DIM + c)       = v0;
            *(float2*)(C + (size_t)(r + 8) * OUT_DIM + c) = v1;
        }
    }
}

// ---------------------------------------------------------------------------
extern "C" void kernel_launch(void* const* d_in, const int* in_sizes, int n_in,
                              void* d_out, int out_size)
{
    const float* x         = (const float*)d_in[0];
    const float* centroids = (const float*)d_in[1];
    const int*   indices   = (const int*)  d_in[2];
    const int*   perm      = (const int*)  d_in[3];
    const float* wscale    = (const float*)d_in[4];
    const float* wbias     = (const float*)d_in[5];
    const float* U         = (const float*)d_in[6];
    const float* S         = (const float*)d_in[7];
    const float* Vt        = (const float*)d_in[8];
    const float* bias      = (const float*)d_in[9];
    float* out = (float*)d_out;

    invperm_kernel<<<IN_DIM / 256, 256>>>(perm);

    fused_pre_kernel<<<8192, 256>>>(x, centroids, indices, wscale, wbias, U, S, Vt);

    cudaFuncSetAttribute(gemm_kernel, cudaFuncAttributeMaxDynamicSharedMemorySize,
                         SMEM_TOTAL);
    gemm_kernel<<<dim3(OUT_DIM / BN, TOKENS / BM), 256, SMEM_TOTAL>>>(bias, out);
}

// round 14
// speedup vs baseline: 1.5754x; 1.5754x over previous
#include <cuda_runtime.h>
#include <cuda_fp16.h>
#include <cstdint>

#define IN_DIM   4096
#define OUT_DIM  4096
#define TOKENS   4096
#define RANK     64
#define VDIM     8
#define NIDX     (IN_DIM / VDIM)

// ---------------------------------------------------------------------------
// Device-global scratch. Everything lives in PERMUTED input space:
//   xp[m][j'] = x[m][invperm[j']],  W'[o][j'] = Q[o][j'] + L'[o][j']
// Single-pass fp16: W stored as plain fp16 (no residual split).
// ---------------------------------------------------------------------------
__device__ __half g_Whi[(size_t)OUT_DIM * IN_DIM];
__device__ __half g_xp[(size_t)TOKENS * IN_DIM];
__device__ int    g_invperm[IN_DIM];

// ---------------------------------------------------------------------------
// PTX helpers (baseline compute_100-legal)
// ---------------------------------------------------------------------------
static __device__ __forceinline__ uint32_t smem_u32(const void* p) {
    uint32_t a;
    asm("{ .reg .u64 t; cvta.to.shared.u64 t, %1; cvt.u32.u64 %0, t; }" : "=r"(a) : "l"(p));
    return a;
}

#define CP_ASYNC16(dst, src) \
    asm volatile("cp.async.cg.shared.global [%0], [%1], 16;\n" :: "r"(dst), "l"(src))
#define CP_COMMIT() asm volatile("cp.async.commit_group;\n" ::: "memory")
#define CP_WAIT1()  asm volatile("cp.async.wait_group 1;\n" ::: "memory")
#define CP_WAIT0()  asm volatile("cp.async.wait_group 0;\n" ::: "memory")

#define LDSM_X4(r0, r1, r2, r3, addr) \
    asm volatile("ldmatrix.sync.aligned.m8n8.x4.shared.b16 {%0,%1,%2,%3}, [%4];" \
        : "=r"(r0), "=r"(r1), "=r"(r2), "=r"(r3) : "r"(addr))

#define MMA16816F(c, a, b) \
    asm volatile("mma.sync.aligned.m16n8k16.row.col.f32.f16.f16.f32 " \
        "{%0,%1,%2,%3}, {%4,%5,%6,%7}, {%8,%9}, {%0,%1,%2,%3};" \
        : "+f"((c)[0]), "+f"((c)[1]), "+f"((c)[2]), "+f"((c)[3]) \
        : "r"((a)[0]), "r"((a)[1]), "r"((a)[2]), "r"((a)[3]), \
          "r"((b)[0]), "r"((b)[1]))

// ---------------------------------------------------------------------------
// Kernel 0: invperm[perm[j]] = j
// ---------------------------------------------------------------------------
__global__ void invperm_kernel(const int* __restrict__ perm)
{
    int j = blockIdx.x * 256 + threadIdx.x;
    g_invperm[perm[j]] = j;
}

// ---------------------------------------------------------------------------
// Kernel 1: dequant in permuted space -> fp16 W' (single array).
//   Tile 32 x 128, 256 threads, thread computes a 4x4 block.
// ---------------------------------------------------------------------------
__global__ __launch_bounds__(256) void dequant_kernel(
    const float* __restrict__ centroids, const int* __restrict__ indices,
    const float* __restrict__ wscale, const float* __restrict__ wbias,
    const float* __restrict__ U, const float* __restrict__ S,
    const float* __restrict__ Vt)
{
    __shared__ float s_us[32 * RANK];      // [ol][r], 8 KB
    __shared__ float s_vt[RANK * 128];     // [r][j'], 32 KB (gathered by invperm)
    __shared__ int   s_inv[128];

    const int o0 = blockIdx.y * 32;
    const int j0 = blockIdx.x * 128;
    const int tid = threadIdx.x;
    const int tr = tid >> 5;               // 0..7  -> rows tr*4 .. tr*4+3
    const int tc = tid & 31;               // 0..31 -> cols tc*4 .. tc*4+3

    if (tid < 128) s_inv[tid] = g_invperm[j0 + tid];
    __syncthreads();

    for (int i = tid; i < 32 * RANK; i += 256) {
        int o = i >> 6, r = i & (RANK - 1);
        s_us[i] = U[(size_t)(o0 + o) * RANK + r] * S[r];
    }
    for (int i = tid; i < RANK * 128; i += 256) {
        int r = i >> 7, j = i & 127;
        s_vt[i] = Vt[(size_t)r * IN_DIM + s_inv[j]];
    }
    __syncthreads();

    // quantized part: 1 index + 1 float4 centroid load per row
    const int grp  = (j0 + tc * 4) >> 3;
    const int coff = (tc * 4) & 7;
    float acc[4][4];
    #pragma unroll
    for (int i = 0; i < 4; i++) {
        int o = o0 + tr * 4 + i;
        int ci = indices[(size_t)o * NIDX + grp];
        float4 cv = *(const float4*)(centroids + (size_t)ci * VDIM + coff);
        float sc = wscale[o], bi = wbias[o];
        acc[i][0] = cv.x * sc + bi;
        acc[i][1] = cv.y * sc + bi;
        acc[i][2] = cv.z * sc + bi;
        acc[i][3] = cv.w * sc + bi;
    }

    // low-rank: 4x4 register block GEMM over RANK
    #pragma unroll
    for (int rb = 0; rb < RANK; rb += 4) {
        float4 us4[4];
        #pragma unroll
        for (int i = 0; i < 4; i++)
            us4[i] = *(const float4*)&s_us[(tr * 4 + i) * RANK + rb];
        #pragma unroll
        for (int rr = 0; rr < 4; rr++) {
            float4 v = *(const float4*)&s_vt[(rb + rr) * 128 + tc * 4];
            #pragma unroll
            for (int i = 0; i < 4; i++) {
                float u = (&us4[i].x)[rr];
                acc[i][0] += u * v.x;
                acc[i][1] += u * v.y;
                acc[i][2] += u * v.z;
                acc[i][3] += u * v.w;
            }
        }
    }

    // store fp16
    #pragma unroll
    for (int i = 0; i < 4; i++) {
        size_t idx = (size_t)(o0 + tr * 4 + i) * IN_DIM + j0 + tc * 4;
        *(__half2*)(g_Whi + idx)     = __floats2half2_rn(acc[i][0], acc[i][1]);
        *(__half2*)(g_Whi + idx + 2) = __floats2half2_rn(acc[i][2], acc[i][3]);
    }
}

// ---------------------------------------------------------------------------
// Kernel 2: xp[m][j'] = fp16(x[m][invperm[j']])
// ---------------------------------------------------------------------------
__global__ __launch_bounds__(256) void convert_x_kernel(const float* __restrict__ x)
{
    size_t i = ((size_t)blockIdx.x * 256 + threadIdx.x) * 4;
    int m = (int)(i >> 12);
    int j = (int)(i & 4095);
    const int4 inv = *(const int4*)(g_invperm + j);
    const float* xr = x + (size_t)m * IN_DIM;
    float v0 = xr[inv.x], v1 = xr[inv.y], v2 = xr[inv.z], v3 = xr[inv.w];
    *(__half2*)(g_xp + i)     = __floats2half2_rn(v0, v1);
    *(__half2*)(g_xp + i + 2) = __floats2half2_rn(v2, v3);
}

// ---------------------------------------------------------------------------
// Kernel 3: single-pass fp16 HMMA GEMM:
//   C = xp * W'^T + bias   (fp32 accumulate)
//   CTA 128x128, BK=64, 8 warps, 2-stage double buffer (2 syncs/iter),
//   2 CTAs/SM. 64 MMAs/warp between barrier pairs.
// ---------------------------------------------------------------------------
#define BM 128
#define BN 128
#define BK 64
#define GKP 72            // padded k-stride (elements); rows at distinct 16B banks
#define NCHUNK (IN_DIM / BK)

#define TILE_BYTES (BM * GKP * 2)          // 18432
#define T_AHI 0
#define T_BHI (1 * TILE_BYTES)
#define STAGE_SZ (2 * TILE_BYTES)          // 36864
#define SMEM_TOTAL (2 * STAGE_SZ)          // 73728  (x2 CTAs = 147456 < 228KB)

static __device__ __forceinline__ void load_chunk(uint32_t stage, int m0, int n0,
                                                  int k0, int tid)
{
    #pragma unroll
    for (int t = 0; t < 4; t++) {
        int idx = t * 256 + tid;
        int row = idx >> 3;                 // 0..127
        int c   = idx & 7;                  // 16B chunk within 128B row
        uint32_t off = (uint32_t)(row * GKP + c * 8) * 2;
        size_t ga = (size_t)(m0 + row) * IN_DIM + k0 + c * 8;
        size_t gb = (size_t)(n0 + row) * IN_DIM + k0 + c * 8;
        CP_ASYNC16(stage + T_AHI + off, (const char*)(g_xp  + ga));
        CP_ASYNC16(stage + T_BHI + off, (const char*)(g_Whi + gb));
    }
    CP_COMMIT();
}

__global__ __launch_bounds__(256, 2) void gemm_kernel(
    const float* __restrict__ bias, float* __restrict__ C)
{
    extern __shared__ char smem[];
    const uint32_t sb = smem_u32(smem);
    const int tid  = threadIdx.x;
    const int wid  = tid >> 5;
    const int lane = tid & 31;
    const int wm   = wid >> 2;              // 0..1 : warp row (64 m each)
    const int wn   = wid & 3;               // 0..3 : warp col (32 n each)
    const int m0   = blockIdx.y * BM;
    const int n0   = blockIdx.x * BN;

    const uint32_t a_off =
        (uint32_t)(((wm * 64 + (lane & 15)) * GKP + ((lane >> 4) & 1) * 8) * 2);
    const uint32_t b_off =
        (uint32_t)(((wn * 32 + ((lane >> 4) & 1) * 8 + (lane & 7)) * GKP +
                    ((lane >> 3) & 1) * 8) * 2);

    float acc[4][4][4];
    #pragma unroll
    for (int i = 0; i < 4; i++)
        #pragma unroll
        for (int j = 0; j < 4; j++)
            #pragma unroll
            for (int k = 0; k < 4; k++) acc[i][j][k] = 0.f;

    // prologue: chunks 0, 1 into stages 0, 1
    load_chunk(sb,            m0, n0, 0,  tid);
    load_chunk(sb + STAGE_SZ, m0, n0, BK, tid);

    for (int i = 0; i < NCHUNK; i++) {
        const uint32_t stage = sb + (i & 1) * STAGE_SZ;
        if (i == NCHUNK - 1) { CP_WAIT0(); } else { CP_WAIT1(); }
        __syncthreads();

        #pragma unroll
        for (int ks = 0; ks < 4; ks++) {
            const uint32_t kb = ks * 32;    // 16 elems * 2B
            uint32_t ahi[4][4], bhi[4][2];
            #pragma unroll
            for (int mi = 0; mi < 4; mi++) {
                uint32_t ad = stage + a_off + mi * (16 * GKP * 2) + kb;
                LDSM_X4(ahi[mi][0], ahi[mi][1], ahi[mi][2], ahi[mi][3], ad + T_AHI);
            }
            #pragma unroll
            for (int g = 0; g < 2; g++) {
                uint32_t bd = stage + b_off + g * (16 * GKP * 2) + kb;
                LDSM_X4(bhi[2*g][0], bhi[2*g][1], bhi[2*g+1][0], bhi[2*g+1][1], bd + T_BHI);
            }
            #pragma unroll
            for (int mi = 0; mi < 4; mi++)
                #pragma unroll
                for (int nj = 0; nj < 4; nj++)
                    MMA16816F(acc[mi][nj], ahi[mi], bhi[nj]);
        }

        // stage (i&1) fully consumed by all warps -> safe to reload with i+2
        __syncthreads();
        if (i + 2 < NCHUNK)
            load_chunk(stage, m0, n0, (i + 2) * BK, tid);
    }

    #pragma unroll
    for (int mi = 0; mi < 4; mi++) {
        int r = m0 + wm * 64 + mi * 16 + (lane >> 2);
        #pragma unroll
        for (int nj = 0; nj < 4; nj++) {
            int c = n0 + wn * 32 + nj * 8 + (lane & 3) * 2;
            float2 bv = *(const float2*)(bias + c);
            float2 v0 = { acc[mi][nj][0] + bv.x, acc[mi][nj][1] + bv.y };
            float2 v1 = { acc[mi][nj][2] + bv.x, acc[mi][nj][3] + bv.y };
            *(float2*)(C + (size_t)r * OUT_DIM + c)       = v0;
            *(float2*)(C + (size_t)(r + 8) * OUT_DIM + c) = v1;
        }
    }
}

// ---------------------------------------------------------------------------
extern "C" void kernel_launch(void* const* d_in, const int* in_sizes, int n_in,
                              void* d_out, int out_size)
{
    const float* x         = (const float*)d_in[0];
    const float* centroids = (const float*)d_in[1];
    const int*   indices   = (const int*)  d_in[2];
    const int*   perm      = (const int*)  d_in[3];
    const float* wscale    = (const float*)d_in[4];
    const float* wbias     = (const float*)d_in[5];
    const float* U         = (const float*)d_in[6];
    const float* S         = (const float*)d_in[7];
    const float* Vt        = (const float*)d_in[8];
    const float* bias      = (const float*)d_in[9];
    float* out = (float*)d_out;

    invperm_kernel<<<IN_DIM / 256, 256>>>(perm);

    convert_x_kernel<<<(TOKENS * (IN_DIM / 4)) / 256, 256>>>(x);

    dequant_kernel<<<dim3(IN_DIM / 128, OUT_DIM / 32), 256>>>(
        centroids, indices, wscale, wbias, U, S, Vt);

    cudaFuncSetAttribute(gemm_kernel, cudaFuncAttributeMaxDynamicSharedMemorySize,
                         SMEM_TOTAL);
    gemm_kernel<<<dim3(OUT_DIM / BN, TOKENS / BM), 256, SMEM_TOTAL>>>(bias, out);
}

// round 16
// speedup vs baseline: 1.8038x; 1.1450x over previous
#include <cuda_runtime.h>
#include <cuda_fp16.h>
#include <cstdint>

#define IN_DIM   4096
#define OUT_DIM  4096
#define TOKENS   4096
#define RANK     64
#define VDIM     8
#define NIDX     (IN_DIM / VDIM)

// ---------------------------------------------------------------------------
// Device-global scratch (permuted input space):
//   xp[m][j'] = fp16(x[m][invperm[j']])
//   Whi[o][j'] = fp16(VQ part only: centroids gather * scale + bias)
//   vtp[r][j'] = fp16(Vt[r][invperm[j']])
//   xvt[m][r]  = sum_j' xp[m][j'] * vtp[r][j']      (fp32, split-K atomics)
//   us[o][r]   = U[o][r] * S[r]                     (fp32)
// out = xp @ Whi^T + xvt @ us^T + bias
// ---------------------------------------------------------------------------
__device__ __half g_Whi[(size_t)OUT_DIM * IN_DIM];
__device__ __half g_xp[(size_t)TOKENS * IN_DIM];
__device__ __half g_vtp[(size_t)RANK * IN_DIM];
__device__ float  g_xvt[(size_t)TOKENS * RANK];
__device__ float  g_us[(size_t)OUT_DIM * RANK];
__device__ int    g_invperm[IN_DIM];

// ---------------------------------------------------------------------------
// PTX helpers (baseline compute_100-legal)
// ---------------------------------------------------------------------------
static __device__ __forceinline__ uint32_t smem_u32(const void* p) {
    uint32_t a;
    asm("{ .reg .u64 t; cvta.to.shared.u64 t, %1; cvt.u32.u64 %0, t; }" : "=r"(a) : "l"(p));
    return a;
}

#define CP_ASYNC16(dst, src) \
    asm volatile("cp.async.cg.shared.global [%0], [%1], 16;\n" :: "r"(dst), "l"(src))
#define CP_COMMIT() asm volatile("cp.async.commit_group;\n" ::: "memory")
#define CP_WAIT1()  asm volatile("cp.async.wait_group 1;\n" ::: "memory")
#define CP_WAIT0()  asm volatile("cp.async.wait_group 0;\n" ::: "memory")

#define LDSM_X4(r0, r1, r2, r3, addr) \
    asm volatile("ldmatrix.sync.aligned.m8n8.x4.shared.b16 {%0,%1,%2,%3}, [%4];" \
        : "=r"(r0), "=r"(r1), "=r"(r2), "=r"(r3) : "r"(addr))

#define MMA16816F(c, a, b) \
    asm volatile("mma.sync.aligned.m16n8k16.row.col.f32.f16.f16.f32 " \
        "{%0,%1,%2,%3}, {%4,%5,%6,%7}, {%8,%9}, {%0,%1,%2,%3};" \
        : "+f"((c)[0]), "+f"((c)[1]), "+f"((c)[2]), "+f"((c)[3]) \
        : "r"((a)[0]), "r"((a)[1]), "r"((a)[2]), "r"((a)[3]), \
          "r"((b)[0]), "r"((b)[1]))

// ---------------------------------------------------------------------------
// Kernel 0: invperm[perm[j]] = j
// ---------------------------------------------------------------------------
__global__ void invperm_kernel(const int* __restrict__ perm)
{
    int j = blockIdx.x * 256 + threadIdx.x;
    g_invperm[perm[j]] = j;
}

// ---------------------------------------------------------------------------
// Kernel 1: prep — vtp gather (fp16), us = U*S, zero xvt. i in [0, 262144).
// ---------------------------------------------------------------------------
__global__ __launch_bounds__(256) void prep_kernel(
    const float* __restrict__ Vt, const float* __restrict__ U,
    const float* __restrict__ S)
{
    int i = blockIdx.x * 256 + threadIdx.x;        // 0..262143 = 64*4096 = 4096*64
    int r = i >> 12, j = i & 4095;
    g_vtp[i] = __float2half_rn(Vt[(size_t)r * IN_DIM + g_invperm[j]]);
    g_us[i]  = U[i] * S[i & (RANK - 1)];
    g_xvt[i] = 0.f;
}

// ---------------------------------------------------------------------------
// Kernel 2: xp[m][j'] = fp16(x[m][invperm[j']])
// ---------------------------------------------------------------------------
__global__ __launch_bounds__(256) void convert_x_kernel(const float* __restrict__ x)
{
    size_t i = ((size_t)blockIdx.x * 256 + threadIdx.x) * 4;
    int m = (int)(i >> 12);
    int j = (int)(i & 4095);
    const int4 inv = *(const int4*)(g_invperm + j);
    const float* xr = x + (size_t)m * IN_DIM;
    float v0 = xr[inv.x], v1 = xr[inv.y], v2 = xr[inv.z], v3 = xr[inv.w];
    *(__half2*)(g_xp + i)     = __floats2half2_rn(v0, v1);
    *(__half2*)(g_xp + i + 2) = __floats2half2_rn(v2, v3);
}

// ---------------------------------------------------------------------------
// Kernel 3: dequant = pure VQ gather + affine -> fp16. One thread per
//   (row, 8-col group): 1 index load + 2 float4 centroid loads + 16B store.
// ---------------------------------------------------------------------------
__global__ __launch_bounds__(256) void dequant_kernel(
    const float* __restrict__ centroids, const int* __restrict__ indices,
    const float* __restrict__ wscale, const float* __restrict__ wbias)
{
    int gidx = blockIdx.x * 256 + threadIdx.x;     // 0 .. 4096*512-1
    int o = gidx >> 9;
    int ci = indices[gidx];
    float4 c0 = *(const float4*)(centroids + (size_t)ci * VDIM);
    float4 c1 = *(const float4*)(centroids + (size_t)ci * VDIM + 4);
    float sc = wscale[o], bi = wbias[o];
    __half2 h[4];
    h[0] = __floats2half2_rn(c0.x * sc + bi, c0.y * sc + bi);
    h[1] = __floats2half2_rn(c0.z * sc + bi, c0.w * sc + bi);
    h[2] = __floats2half2_rn(c1.x * sc + bi, c1.y * sc + bi);
    h[3] = __floats2half2_rn(c1.z * sc + bi, c1.w * sc + bi);
    *(uint4*)(g_Whi + (size_t)gidx * 8) = *(uint4*)h;
}

// ---------------------------------------------------------------------------
// Kernel 4: xvt HMMA — xvt[m][r] += sum over K-split of xp[m][k]*vtp[r][k].
//   CTA tile M=128, N=64 (all RANK), K-split 8 x 512, BK=64, 8 warps
//   (warp tile 32x32), 2-stage double buffer, fp32 atomicAdd epilogue.
// ---------------------------------------------------------------------------
#define GKP 72            // padded k-stride (elements)
#define XBK 64
#define XK_LEN 512
#define XNCH (XK_LEN / XBK)   // 8 chunks per split

#define XA_TILE (128 * GKP * 2)        // 18432
#define XB_TILE (64 * GKP * 2)         // 9216
#define XSTAGE (XA_TILE + XB_TILE)     // 27648
#define XSMEM  (2 * XSTAGE)            // 55296

static __device__ __forceinline__ void xvt_load(uint32_t stage, int m0, int k0, int tid)
{
    #pragma unroll
    for (int t = 0; t < 4; t++) {       // A: 128 rows x 8 x 16B
        int idx = t * 256 + tid;
        int row = idx >> 3, c = idx & 7;
        uint32_t off = (uint32_t)(row * GKP + c * 8) * 2;
        CP_ASYNC16(stage + off, (const char*)(g_xp + (size_t)(m0 + row) * IN_DIM + k0 + c * 8));
    }
    #pragma unroll
    for (int t = 0; t < 2; t++) {       // B: 64 rows x 8 x 16B
        int idx = t * 256 + tid;
        int row = idx >> 3, c = idx & 7;
        uint32_t off = (uint32_t)(row * GKP + c * 8) * 2;
        CP_ASYNC16(stage + XA_TILE + off, (const char*)(g_vtp + (size_t)row * IN_DIM + k0 + c * 8));
    }
    CP_COMMIT();
}

__global__ __launch_bounds__(256, 2) void xvt_kernel()
{
    extern __shared__ char smem[];
    const uint32_t sb = smem_u32(smem);
    const int tid  = threadIdx.x;
    const int wid  = tid >> 5;
    const int lane = tid & 31;
    const int wm2  = wid >> 1;          // 0..3 : 32 m-rows each
    const int wn2  = wid & 1;           // 0..1 : 32 r-cols each
    const int ksplit = blockIdx.x;      // 0..7
    const int m0     = blockIdx.y * 128;
    const int kbase  = ksplit * XK_LEN;

    const uint32_t a_off =
        (uint32_t)(((wm2 * 32 + (lane & 15)) * GKP + ((lane >> 4) & 1) * 8) * 2);
    const uint32_t b_off =
        (uint32_t)(((wn2 * 32 + ((lane >> 4) & 1) * 8 + (lane & 7)) * GKP +
                    ((lane >> 3) & 1) * 8) * 2);

    float acc[2][4][4];
    #pragma unroll
    for (int i = 0; i < 2; i++)
        #pragma unroll
        for (int j = 0; j < 4; j++)
            #pragma unroll
            for (int k = 0; k < 4; k++) acc[i][j][k] = 0.f;

    xvt_load(sb,          m0, kbase,       tid);
    xvt_load(sb + XSTAGE, m0, kbase + XBK, tid);

    for (int i = 0; i < XNCH; i++) {
        const uint32_t stage = sb + (i & 1) * XSTAGE;
        if (i == XNCH - 1) { CP_WAIT0(); } else { CP_WAIT1(); }
        __syncthreads();

        #pragma unroll
        for (int ks = 0; ks < 4; ks++) {
            const uint32_t kb = ks * 32;
            uint32_t af[2][4], bf[4][2];
            #pragma unroll
            for (int mi = 0; mi < 2; mi++) {
                uint32_t ad = stage + a_off + mi * (16 * GKP * 2) + kb;
                LDSM_X4(af[mi][0], af[mi][1], af[mi][2], af[mi][3], ad);
            }
            #pragma unroll
            for (int g = 0; g < 2; g++) {
                uint32_t bd = stage + XA_TILE + b_off + g * (16 * GKP * 2) + kb;
                LDSM_X4(bf[2*g][0], bf[2*g][1], bf[2*g+1][0], bf[2*g+1][1], bd);
            }
            #pragma unroll
            for (int mi = 0; mi < 2; mi++)
                #pragma unroll
                for (int nj = 0; nj < 4; nj++)
                    MMA16816F(acc[mi][nj], af[mi], bf[nj]);
        }

        __syncthreads();
        if (i + 2 < XNCH)
            xvt_load(stage, m0, kbase + (i + 2) * XBK, tid);
    }

    #pragma unroll
    for (int mi = 0; mi < 2; mi++) {
        int rrow = m0 + wm2 * 32 + mi * 16 + (lane >> 2);
        #pragma unroll
        for (int nj = 0; nj < 4; nj++) {
            int ccol = wn2 * 32 + nj * 8 + (lane & 3) * 2;
            atomicAdd(&g_xvt[(size_t)rrow * RANK + ccol],           acc[mi][nj][0]);
            atomicAdd(&g_xvt[(size_t)rrow * RANK + ccol + 1],       acc[mi][nj][1]);
            atomicAdd(&g_xvt[(size_t)(rrow + 8) * RANK + ccol],     acc[mi][nj][2]);
            atomicAdd(&g_xvt[(size_t)(rrow + 8) * RANK + ccol + 1], acc[mi][nj][3]);
        }
    }
}

// ---------------------------------------------------------------------------
// Kernel 5: main GEMM (single-pass fp16 HMMA) + fp32 low-rank epilogue:
//   C = xp*Whi^T + xvt*us^T + bias
//   CTA 128x128, BK=64, 8 warps, 2-stage double buffer, 2 CTAs/SM.
// ---------------------------------------------------------------------------
#define BM 128
#define BN 128
#define BK 64
#define NCHUNK (IN_DIM / BK)

#define TILE_BYTES (BM * GKP * 2)          // 18432
#define T_AHI 0
#define T_BHI (1 * TILE_BYTES)
#define STAGE_SZ (2 * TILE_BYTES)          // 36864
#define SMEM_TOTAL (2 * STAGE_SZ)          // 73728  (epilogue reuses: 2*128*65*4 = 66560)

static __device__ __forceinline__ void load_chunk(uint32_t stage, int m0, int n0,
                                                  int k0, int tid)
{
    #pragma unroll
    for (int t = 0; t < 4; t++) {
        int idx = t * 256 + tid;
        int row = idx >> 3;                 // 0..127
        int c   = idx & 7;                  // 16B chunk within 128B row
        uint32_t off = (uint32_t)(row * GKP + c * 8) * 2;
        size_t ga = (size_t)(m0 + row) * IN_DIM + k0 + c * 8;
        size_t gb = (size_t)(n0 + row) * IN_DIM + k0 + c * 8;
        CP_ASYNC16(stage + T_AHI + off, (const char*)(g_xp  + ga));
        CP_ASYNC16(stage + T_BHI + off, (const char*)(g_Whi + gb));
    }
    CP_COMMIT();
}

__global__ __launch_bounds__(256, 2) void gemm_kernel(
    const float* __restrict__ bias, float* __restrict__ C)
{
    extern __shared__ char smem[];
    const uint32_t sb = smem_u32(smem);
    const int tid  = threadIdx.x;
    const int wid  = tid >> 5;
    const int lane = tid & 31;
    const int wm   = wid >> 2;              // 0..1 : warp row (64 m each)
    const int wn   = wid & 3;               // 0..3 : warp col (32 n each)
    const int m0   = blockIdx.y * BM;
    const int n0   = blockIdx.x * BN;

    const uint32_t a_off =
        (uint32_t)(((wm * 64 + (lane & 15)) * GKP + ((lane >> 4) & 1) * 8) * 2);
    const uint32_t b_off =
        (uint32_t)(((wn * 32 + ((lane >> 4) & 1) * 8 + (lane & 7)) * GKP +
                    ((lane >> 3) & 1) * 8) * 2);

    float acc[4][4][4];
    #pragma unroll
    for (int i = 0; i < 4; i++)
        #pragma unroll
        for (int j = 0; j < 4; j++)
            #pragma unroll
            for (int k = 0; k < 4; k++) acc[i][j][k] = 0.f;

    load_chunk(sb,            m0, n0, 0,  tid);
    load_chunk(sb + STAGE_SZ, m0, n0, BK, tid);

    for (int i = 0; i < NCHUNK; i++) {
        const uint32_t stage = sb + (i & 1) * STAGE_SZ;
        if (i == NCHUNK - 1) { CP_WAIT0(); } else { CP_WAIT1(); }
        __syncthreads();

        #pragma unroll
        for (int ks = 0; ks < 4; ks++) {
            const uint32_t kb = ks * 32;    // 16 elems * 2B
            uint32_t ahi[4][4], bhi[4][2];
            #pragma unroll
            for (int mi = 0; mi < 4; mi++) {
                uint32_t ad = stage + a_off + mi * (16 * GKP * 2) + kb;
                LDSM_X4(ahi[mi][0], ahi[mi][1], ahi[mi][2], ahi[mi][3], ad + T_AHI);
            }
            #pragma unroll
            for (int g = 0; g < 2; g++) {
                uint32_t bd = stage + b_off + g * (16 * GKP * 2) + kb;
                LDSM_X4(bhi[2*g][0], bhi[2*g][1], bhi[2*g+1][0], bhi[2*g+1][1], bd + T_BHI);
            }
            #pragma unroll
            for (int mi = 0; mi < 4; mi++)
                #pragma unroll
                for (int nj = 0; nj < 4; nj++)
                    MMA16816F(acc[mi][nj], ahi[mi], bhi[nj]);
        }

        __syncthreads();
        if (i + 2 < NCHUNK)
            load_chunk(stage, m0, n0, (i + 2) * BK, tid);
    }
    // final __syncthreads of the loop guarantees all warps are done with smem

    // ---- low-rank epilogue: acc += xvt[m0 tile] @ us[n0 tile]^T (fp32) ----
    float* sx = (float*)smem;               // [128][65]
    float* su = (float*)(smem + 128 * 65 * 4);
    for (int idx = tid; idx < 8192; idx += 256) {
        int row = idx >> 6, r = idx & 63;
        sx[row * 65 + r] = g_xvt[(size_t)(m0 + row) * RANK + r];
        su[row * 65 + r] = g_us[(size_t)(n0 + row) * RANK + r];
    }
    __syncthreads();

    {
        const int lq = lane >> 2;
        const int l2 = (lane & 3) * 2;
        const float* sxb = sx + (wm * 64 + lq) * 65;
        const float* sub = su + (wn * 32 + l2) * 65;
        for (int r = 0; r < RANK; r++) {
            float xv[8], uu[8];
            #pragma unroll
            for (int mi = 0; mi < 4; mi++) {
                xv[mi * 2]     = sxb[(mi * 16) * 65 + r];
                xv[mi * 2 + 1] = sxb[(mi * 16 + 8) * 65 + r];
            }
            #pragma unroll
            for (int nj = 0; nj < 4; nj++) {
                uu[nj * 2]     = sub[(nj * 8) * 65 + r];
                uu[nj * 2 + 1] = sub[(nj * 8 + 1) * 65 + r];
            }
            #pragma unroll
            for (int mi = 0; mi < 4; mi++)
                #pragma unroll
                for (int nj = 0; nj < 4; nj++) {
                    acc[mi][nj][0] += xv[mi * 2]     * uu[nj * 2];
                    acc[mi][nj][1] += xv[mi * 2]     * uu[nj * 2 + 1];
                    acc[mi][nj][2] += xv[mi * 2 + 1] * uu[nj * 2];
                    acc[mi][nj][3] += xv[mi * 2 + 1] * uu[nj * 2 + 1];
                }
        }
    }

    #pragma unroll
    for (int mi = 0; mi < 4; mi++) {
        int r = m0 + wm * 64 + mi * 16 + (lane >> 2);
        #pragma unroll
        for (int nj = 0; nj < 4; nj++) {
            int c = n0 + wn * 32 + nj * 8 + (lane & 3) * 2;
            float2 bv = *(const float2*)(bias + c);
            float2 v0 = { acc[mi][nj][0] + bv.x, acc[mi][nj][1] + bv.y };
            float2 v1 = { acc[mi][nj][2] + bv.x, acc[mi][nj][3] + bv.y };
            *(float2*)(C + (size_t)r * OUT_DIM + c)       = v0;
            *(float2*)(C + (size_t)(r + 8) * OUT_DIM + c) = v1;
        }
    }
}

// ---------------------------------------------------------------------------
extern "C" void kernel_launch(void* const* d_in, const int* in_sizes, int n_in,
                              void* d_out, int out_size)
{
    const float* x         = (const float*)d_in[0];
    const float* centroids = (const float*)d_in[1];
    const int*   indices   = (const int*)  d_in[2];
    const int*   perm      = (const int*)  d_in[3];
    const float* wscale    = (const float*)d_in[4];
    const float* wbias     = (const float*)d_in[5];
    const float* U         = (const float*)d_in[6];
    const float* S         = (const float*)d_in[7];
    const float* Vt        = (const float*)d_in[8];
    const float* bias      = (const float*)d_in[9];
    float* out = (float*)d_out;

    invperm_kernel<<<IN_DIM / 256, 256>>>(perm);
    prep_kernel<<<(RANK * IN_DIM) / 256, 256>>>(Vt, U, S);
    convert_x_kernel<<<(TOKENS * (IN_DIM / 4)) / 256, 256>>>(x);
    dequant_kernel<<<(OUT_DIM * NIDX) / 256, 256>>>(centroids, indices, wscale, wbias);

    cudaFuncSetAttribute(xvt_kernel, cudaFuncAttributeMaxDynamicSharedMemorySize,
                         XSMEM);
    xvt_kernel<<<dim3(8, TOKENS / 128), 256, XSMEM>>>();

    cudaFuncSetAttribute(gemm_kernel, cudaFuncAttributeMaxDynamicSharedMemorySize,
                         SMEM_TOTAL);
    gemm_kernel<<<dim3(OUT_DIM / BN, TOKENS / BM), 256, SMEM_TOTAL>>>(bias, out);
}